// round 11
// baseline (speedup 1.0000x reference)
#include <cuda_runtime.h>
#include <cuda_bf16.h>
#include <cstdint>
#include <cstddef>

// ===========================================================================
// GCN via bf16-split warp MMA (mma.sync m16n8k16, fp32 accum).
//   A*B ~= Ahi*Bhi + Ahi*Blo + Alo*Bhi
// B=32, N=1024, D=256, NHID=512, NHID_HALF=256, NCLASS=2
// 3-stage cp.async ring, single __syncthreads per K-chunk.
// ===========================================================================

#define NBAT 32
#define NNODE 1024
#define HMAX (NBAT * NNODE * 512)

__device__ __nv_bfloat16 g_adjh[NBAT * NNODE * NNODE];
__device__ __nv_bfloat16 g_adjl[NBAT * NNODE * NNODE];
__device__ __nv_bfloat16 g_h0h[HMAX], g_h0l[HMAX], g_h1h[HMAX], g_h1l[HMAX];
__device__ __nv_bfloat16 g_agh[HMAX], g_agl[HMAX];
__device__ float g_cls[NBAT * NNODE * 256];
__device__ __nv_bfloat16 g_wh[1310720], g_wl[1310720];

// ---------------------------------------------------------------------------
static __device__ __forceinline__ uint32_t s2u(const void* p) {
    uint32_t a;
    asm("{ .reg .u64 t; cvta.to.shared.u64 t, %1; cvt.u32.u64 %0, t; }" : "=r"(a) : "l"(p));
    return a;
}
static __device__ __forceinline__ void split2(float v, __nv_bfloat16& h, __nv_bfloat16& l) {
    h = __float2bfloat16(v);
    l = __float2bfloat16(v - __bfloat162float(h));
}
#define SWZ(x) ((x) ^ (((x) >> 3) & 0x70))

static __device__ __forceinline__ void cp16(uint32_t dst, const void* src) {
    asm volatile("cp.async.cg.shared.global [%0], [%1], 16;" :: "r"(dst), "l"(src));
}
static __device__ __forceinline__ void ldsm4(uint32_t* r, uint32_t addr) {
    asm volatile("ldmatrix.sync.aligned.m8n8.x4.shared.b16 {%0,%1,%2,%3}, [%4];"
                 : "=r"(r[0]), "=r"(r[1]), "=r"(r[2]), "=r"(r[3]) : "r"(addr));
}
static __device__ __forceinline__ void ldsm4t(uint32_t* r, uint32_t addr) {
    asm volatile("ldmatrix.sync.aligned.m8n8.x4.trans.shared.b16 {%0,%1,%2,%3}, [%4];"
                 : "=r"(r[0]), "=r"(r[1]), "=r"(r[2]), "=r"(r[3]) : "r"(addr));
}
static __device__ __forceinline__ void mma16816(float* c, const uint32_t* a, const uint32_t* b) {
    asm volatile(
        "mma.sync.aligned.m16n8k16.row.col.f32.bf16.bf16.f32 "
        "{%0,%1,%2,%3}, {%4,%5,%6,%7}, {%8,%9}, {%0,%1,%2,%3};"
        : "+f"(c[0]), "+f"(c[1]), "+f"(c[2]), "+f"(c[3])
        : "r"(a[0]), "r"(a[1]), "r"(a[2]), "r"(a[3]), "r"(b[0]), "r"(b[1]));
}

// ---------------------------------------------------------------------------
// Generic fp32 -> bf16 hi/lo splitter (vectorized by 4)
// ---------------------------------------------------------------------------
__global__ void split_kernel(const float4* __restrict__ src,
                             __nv_bfloat16* __restrict__ hi,
                             __nv_bfloat16* __restrict__ lo, int n4) {
    int i = blockIdx.x * blockDim.x + threadIdx.x;
    if (i >= n4) return;
    float4 v = src[i];
    __nv_bfloat16 h0, l0, h1, l1, h2, l2, h3, l3;
    split2(v.x, h0, l0); split2(v.y, h1, l1);
    split2(v.z, h2, l2); split2(v.w, h3, l3);
    __nv_bfloat162 a, b, c, d;
    a.x = h0; a.y = h1; b.x = h2; b.y = h3;
    c.x = l0; c.y = l1; d.x = l2; d.y = l3;
    __nv_bfloat162* ph = reinterpret_cast<__nv_bfloat162*>(hi) + (size_t)i * 2;
    __nv_bfloat162* pl = reinterpret_cast<__nv_bfloat162*>(lo) + (size_t)i * 2;
    ph[0] = a; ph[1] = b;
    pl[0] = c; pl[1] = d;
}

// ---------------------------------------------------------------------------
// Split-bf16 warp-MMA GEMM:  D[M,N] = A[M,K] @ B[K,N]   (both row-major)
// A virtually split at ksplit: k<ksplit -> A0 (lda=ksplit), else A1 (lda=K-ksplit)
// EPI: 0 = split store, 1 = bias+relu -> split store, 3 = bias+prelu -> fp32
// M,N multiples of 128; K,ksplit multiples of 64.
// ---------------------------------------------------------------------------
#define STGB 65536
#define NSTG 3
#define SMEM_BYTES (NSTG * STGB + 1024)

template <int EPI>
__global__ void __launch_bounds__(256, 1)
tc_gemm(const __nv_bfloat16* __restrict__ A0h, const __nv_bfloat16* __restrict__ A0l,
        const __nv_bfloat16* __restrict__ A1h, const __nv_bfloat16* __restrict__ A1l,
        int ksplit,
        const __nv_bfloat16* __restrict__ Bh, const __nv_bfloat16* __restrict__ Bl,
        const float* __restrict__ bias, const float* __restrict__ alpha,
        float* __restrict__ Cf,
        __nv_bfloat16* __restrict__ Chi, __nv_bfloat16* __restrict__ Clo,
        int M, int N, int K, long sA, long sB)
{
    extern __shared__ char smraw[];
    const int tid = threadIdx.x;
    const int bz = blockIdx.z;
    const int row0 = blockIdx.y * 128, col0 = blockIdx.x * 128;
    uint32_t sb0 = (s2u(smraw) + 1023u) & ~1023u;

    const __nv_bfloat16* A0hb = A0h + (size_t)bz * sA;
    const __nv_bfloat16* A0lb = A0l + (size_t)bz * sA;
    const __nv_bfloat16* A1hb = A1h + (size_t)bz * sA;
    const __nv_bfloat16* A1lb = A1l + (size_t)bz * sA;
    const __nv_bfloat16* Bhb  = Bh + (size_t)bz * sB;
    const __nv_bfloat16* Blb  = Bl + (size_t)bz * sB;
    const int NT = K >> 6;

    // per-thread load coords
    const int ar = tid >> 1;            // A row 0..127
    const int acb = (tid & 1) * 4;      // A chunk base (of 8 16B chunks/row)
    const int bk = tid >> 2;            // B k-row 0..63
    const int bcb = (tid & 3) * 4;      // B chunk base (of 16 16B chunks/row)

    auto load_stage = [&](int t) {
        uint32_t ub = sb0 + (t % NSTG) * STGB;
        int k0 = t << 6;
        const __nv_bfloat16 *pAh, *pAl;
        int lda, kk;
        if (k0 < ksplit) { pAh = A0hb; pAl = A0lb; lda = ksplit; kk = k0; }
        else             { pAh = A1hb; pAl = A1lb; lda = K - ksplit; kk = k0 - ksplit; }
        const __nv_bfloat16* arh = pAh + (size_t)(row0 + ar) * lda + kk;
        const __nv_bfloat16* arl = pAl + (size_t)(row0 + ar) * lda + kk;
        const __nv_bfloat16* brh = Bhb + (size_t)(k0 + bk) * N + col0;
        const __nv_bfloat16* brl = Blb + (size_t)(k0 + bk) * N + col0;
#pragma unroll
        for (int c = 0; c < 4; c++) {
            uint32_t so = SWZ((uint32_t)(ar * 128 + (acb + c) * 16));
            cp16(ub + so,         arh + (acb + c) * 8);
            cp16(ub + 16384 + so, arl + (acb + c) * 8);
            uint32_t bo = (uint32_t)(bk * 256 + (((bcb + c) ^ (bk & 7)) * 16));
            cp16(ub + 32768 + bo, brh + (bcb + c) * 8);
            cp16(ub + 49152 + bo, brl + (bcb + c) * 8);
        }
        asm volatile("cp.async.commit_group;" ::: "memory");
    };

    load_stage(0);
    if (NT > 1) load_stage(1);

    const int wid = tid >> 5, lane = tid & 31;
    const int m0 = (wid >> 2) * 64;      // warp m offset in tile
    const int nw = (wid & 3) * 32;       // warp n offset in tile

    float acc[4][4][4];
#pragma unroll
    for (int a = 0; a < 4; a++)
#pragma unroll
        for (int b = 0; b < 4; b++)
#pragma unroll
            for (int c = 0; c < 4; c++) acc[a][b][c] = 0.0f;

    // ldmatrix lane addressing
    const int a_row = (lane & 15);
    const int a_seg = (lane >> 4);
    const int b_row = (lane & 7) + ((lane >> 3) & 1) * 8;
    const int b_seg = (lane >> 4);

    for (int t = 0; t < NT; t++) {
        // group t complete (per-thread) ...
        if (t < NT - 1) asm volatile("cp.async.wait_group 1;" ::: "memory");
        else            asm volatile("cp.async.wait_group 0;" ::: "memory");
        // ... then make visible to all warps; also guarantees compute(t-1)
        // finished everywhere so buf (t+2)%3 is free to overwrite.
        __syncthreads();
        if (t + 2 < NT) load_stage(t + 2);

        uint32_t ub = sb0 + (t % NSTG) * STGB;
#pragma unroll
        for (int k16 = 0; k16 < 4; k16++) {
            uint32_t Ah[4][4], Al[4][4];
#pragma unroll
            for (int mi = 0; mi < 4; mi++) {
                int row = m0 + mi * 16 + a_row;
                uint32_t off = SWZ((uint32_t)(row * 128 + (k16 * 2 + a_seg) * 16));
                ldsm4(Ah[mi], ub + off);
                ldsm4(Al[mi], ub + 16384 + off);
            }
#pragma unroll
            for (int p = 0; p < 2; p++) {
                int kr = k16 * 16 + b_row;
                int nseg = ((nw + p * 16) >> 3) + b_seg;
                uint32_t off = (uint32_t)(kr * 256 + ((nseg ^ (kr & 7)) * 16));
                uint32_t Bh4[4], Bl4[4];
                ldsm4t(Bh4, ub + 32768 + off);
                ldsm4t(Bl4, ub + 49152 + off);
#pragma unroll
                for (int q = 0; q < 2; q++) {
                    const int ni = p * 2 + q;
#pragma unroll
                    for (int mi = 0; mi < 4; mi++) {
                        mma16816(acc[mi][ni], Ah[mi], &Bh4[q * 2]);
                        mma16816(acc[mi][ni], Ah[mi], &Bl4[q * 2]);
                        mma16816(acc[mi][ni], Al[mi], &Bh4[q * 2]);
                    }
                }
            }
        }
    }

    // ---- epilogue ----
    const int r_lane = lane >> 2;
    const int c_lane = (lane & 3) * 2;
#pragma unroll
    for (int mi = 0; mi < 4; mi++) {
#pragma unroll
        for (int ni = 0; ni < 4; ni++) {
            int rg = row0 + m0 + mi * 16 + r_lane;
            int cg = col0 + nw + ni * 8 + c_lane;
            long grow0 = (long)bz * M + rg;
            long grow1 = grow0 + 8;
            float v0 = acc[mi][ni][0], v1 = acc[mi][ni][1];
            float v2 = acc[mi][ni][2], v3 = acc[mi][ni][3];
            if (EPI == 1) {
                float bb0 = __ldg(bias + cg), bb1 = __ldg(bias + cg + 1);
                v0 = fmaxf(v0 + bb0, 0.0f); v1 = fmaxf(v1 + bb1, 0.0f);
                v2 = fmaxf(v2 + bb0, 0.0f); v3 = fmaxf(v3 + bb1, 0.0f);
            }
            if (EPI == 3) {
                float bb0 = __ldg(bias + cg), bb1 = __ldg(bias + cg + 1);
                float aa0 = __ldg(alpha + cg), aa1 = __ldg(alpha + cg + 1);
                v0 += bb0; v1 += bb1; v2 += bb0; v3 += bb1;
                v0 = v0 > 0.0f ? v0 : aa0 * v0;
                v1 = v1 > 0.0f ? v1 : aa1 * v1;
                v2 = v2 > 0.0f ? v2 : aa0 * v2;
                v3 = v3 > 0.0f ? v3 : aa1 * v3;
                float2 f0; f0.x = v0; f0.y = v1;
                float2 f1; f1.x = v2; f1.y = v3;
                *reinterpret_cast<float2*>(Cf + grow0 * N + cg) = f0;
                *reinterpret_cast<float2*>(Cf + grow1 * N + cg) = f1;
            } else {
                __nv_bfloat16 h0, l0, h1, l1, h2, l2, h3, l3;
                split2(v0, h0, l0); split2(v1, h1, l1);
                split2(v2, h2, l2); split2(v3, h3, l3);
                __nv_bfloat162 hp0, lp0, hp1, lp1;
                hp0.x = h0; hp0.y = h1; lp0.x = l0; lp0.y = l1;
                hp1.x = h2; hp1.y = h3; lp1.x = l2; lp1.y = l3;
                *reinterpret_cast<__nv_bfloat162*>(Chi + grow0 * N + cg) = hp0;
                *reinterpret_cast<__nv_bfloat162*>(Clo + grow0 * N + cg) = lp0;
                *reinterpret_cast<__nv_bfloat162*>(Chi + grow1 * N + cg) = hp1;
                *reinterpret_cast<__nv_bfloat162*>(Clo + grow1 * N + cg) = lp1;
            }
        }
    }
}

// ---------------------------------------------------------------------------
// Final classifier: out[r, 0:2] = h[r, :] @ cW2[256,2] + cb2
// ---------------------------------------------------------------------------
__global__ void cls2_kernel(const float* __restrict__ h, const float* __restrict__ W,
                            const float* __restrict__ bvec, float* __restrict__ out, int M)
{
    __shared__ float Ws[512];
    const int tid = threadIdx.x;
    for (int i = tid; i < 512; i += blockDim.x) Ws[i] = W[i];
    __syncthreads();
    const int r = blockIdx.x * blockDim.x + tid;
    if (r >= M) return;
    const float4* hr = reinterpret_cast<const float4*>(h + (size_t)r * 256);
    float s0 = bvec[0], s1 = bvec[1];
#pragma unroll 8
    for (int k4 = 0; k4 < 64; k4++) {
        float4 v = hr[k4];
        const int k = k4 * 4;
        s0 = fmaf(v.x, Ws[(k + 0) * 2 + 0], s0);
        s1 = fmaf(v.x, Ws[(k + 0) * 2 + 1], s1);
        s0 = fmaf(v.y, Ws[(k + 1) * 2 + 0], s0);
        s1 = fmaf(v.y, Ws[(k + 1) * 2 + 1], s1);
        s0 = fmaf(v.z, Ws[(k + 2) * 2 + 0], s0);
        s1 = fmaf(v.z, Ws[(k + 2) * 2 + 1], s1);
        s0 = fmaf(v.w, Ws[(k + 3) * 2 + 0], s0);
        s1 = fmaf(v.w, Ws[(k + 3) * 2 + 1], s1);
    }
    out[(size_t)r * 2 + 0] = s0;
    out[(size_t)r * 2 + 1] = s1;
}

// ---------------------------------------------------------------------------
extern "C" void kernel_launch(void* const* d_in, const int* in_sizes, int n_in,
                              void* d_out, int out_size)
{
    const float* x   = (const float*)d_in[0];
    const float* adj = (const float*)d_in[1];
    const float* W1  = (const float*)d_in[2];
    const float* b1  = (const float*)d_in[3];
    const float* W2  = (const float*)d_in[4];
    const float* b2  = (const float*)d_in[5];
    const float* W3  = (const float*)d_in[6];
    const float* b3  = (const float*)d_in[7];
    const float* W4  = (const float*)d_in[8];
    const float* b4  = (const float*)d_in[9];
    const float* cW1 = (const float*)d_in[10];
    const float* cb1 = (const float*)d_in[11];
    const float* alp = (const float*)d_in[12];
    const float* cW2 = (const float*)d_in[13];
    const float* cb2 = (const float*)d_in[14];
    float* out = (float*)d_out;

    cudaFuncSetAttribute(tc_gemm<0>, cudaFuncAttributeMaxDynamicSharedMemorySize, SMEM_BYTES);
    cudaFuncSetAttribute(tc_gemm<1>, cudaFuncAttributeMaxDynamicSharedMemorySize, SMEM_BYTES);
    cudaFuncSetAttribute(tc_gemm<3>, cudaFuncAttributeMaxDynamicSharedMemorySize, SMEM_BYTES);

    __nv_bfloat16 *adjh, *adjl, *h0h, *h0l, *h1h, *h1l, *agh, *agl, *wh, *wl;
    float* cls;
    cudaGetSymbolAddress((void**)&adjh, g_adjh);
    cudaGetSymbolAddress((void**)&adjl, g_adjl);
    cudaGetSymbolAddress((void**)&h0h, g_h0h);
    cudaGetSymbolAddress((void**)&h0l, g_h0l);
    cudaGetSymbolAddress((void**)&h1h, g_h1h);
    cudaGetSymbolAddress((void**)&h1l, g_h1l);
    cudaGetSymbolAddress((void**)&agh, g_agh);
    cudaGetSymbolAddress((void**)&agl, g_agl);
    cudaGetSymbolAddress((void**)&wh, g_wh);
    cudaGetSymbolAddress((void**)&wl, g_wl);
    cudaGetSymbolAddress((void**)&cls, g_cls);

    const long aS = (long)NNODE * NNODE;
    dim3 blk(256);

    // ---- prep: elementwise bf16 hi/lo splits
    split_kernel<<<(NBAT * NNODE * NNODE / 4 + 255) / 256, blk>>>(
        (const float4*)adj, adjh, adjl, NBAT * NNODE * NNODE / 4);
    split_kernel<<<(NBAT * NNODE * 256 / 4 + 255) / 256, blk>>>(
        (const float4*)x, h0h, h0l, NBAT * NNODE * 256 / 4);
    split_kernel<<<(262144 / 4 + 255) / 256, blk>>>((const float4*)W1, wh + 0, wl + 0, 65536);
    split_kernel<<<(524288 / 4 + 255) / 256, blk>>>((const float4*)W2, wh + 262144, wl + 262144, 131072);
    split_kernel<<<(262144 / 4 + 255) / 256, blk>>>((const float4*)W3, wh + 786432, wl + 786432, 65536);
    split_kernel<<<(131072 / 4 + 255) / 256, blk>>>((const float4*)W4, wh + 1048576, wl + 1048576, 32768);
    split_kernel<<<(65536 / 4 + 255) / 256, blk>>>((const float4*)cW1, wh + 1179648, wl + 1179648, 16384);

    // ---- Layer 1: agg = adj @ x (N=256); h1 = relu([x|agg] @ W1) (N=512)
    tc_gemm<0><<<dim3(2, 8, NBAT), blk, SMEM_BYTES>>>(
        adjh, adjl, adjh, adjl, 1024, h0h, h0l, nullptr, nullptr,
        nullptr, agh, agl, 1024, 256, 1024, aS, (long)NNODE * 256);
    tc_gemm<1><<<dim3(4, 256, 1), blk, SMEM_BYTES>>>(
        h0h, h0l, agh, agl, 256, wh + 0, wl + 0, b1, nullptr,
        nullptr, h1h, h1l, 32768, 512, 512, 0, 0);

    // ---- Layer 2
    tc_gemm<0><<<dim3(4, 8, NBAT), blk, SMEM_BYTES>>>(
        adjh, adjl, adjh, adjl, 1024, h1h, h1l, nullptr, nullptr,
        nullptr, agh, agl, 1024, 512, 1024, aS, (long)NNODE * 512);
    tc_gemm<1><<<dim3(4, 256, 1), blk, SMEM_BYTES>>>(
        h1h, h1l, agh, agl, 512, wh + 262144, wl + 262144, b2, nullptr,
        nullptr, h0h, h0l, 32768, 512, 1024, 0, 0);

    // ---- Layer 3
    tc_gemm<0><<<dim3(4, 8, NBAT), blk, SMEM_BYTES>>>(
        adjh, adjl, adjh, adjl, 1024, h0h, h0l, nullptr, nullptr,
        nullptr, agh, agl, 1024, 512, 1024, aS, (long)NNODE * 512);
    tc_gemm<1><<<dim3(2, 256, 1), blk, SMEM_BYTES>>>(
        h0h, h0l, agh, agl, 512, wh + 786432, wl + 786432, b3, nullptr,
        nullptr, h1h, h1l, 32768, 256, 1024, 0, 0);

    // ---- Layer 4
    tc_gemm<0><<<dim3(2, 8, NBAT), blk, SMEM_BYTES>>>(
        adjh, adjl, adjh, adjl, 1024, h1h, h1l, nullptr, nullptr,
        nullptr, agh, agl, 1024, 256, 1024, aS, (long)NNODE * 256);
    tc_gemm<1><<<dim3(2, 256, 1), blk, SMEM_BYTES>>>(
        h1h, h1l, agh, agl, 256, wh + 1048576, wl + 1048576, b4, nullptr,
        nullptr, h0h, h0l, 32768, 256, 512, 0, 0);

    // ---- Classifier
    tc_gemm<3><<<dim3(2, 256, 1), blk, SMEM_BYTES>>>(
        h0h, h0l, h0h, h0l, 256, wh + 1179648, wl + 1179648, cb1, alp,
        cls, nullptr, nullptr, 32768, 256, 256, 0, 0);
    cls2_kernel<<<dim3(128), blk>>>(cls, cW2, cb2, out, 32768);
}

// round 13
// speedup vs baseline: 1.2210x; 1.2210x over previous
#include <cuda_runtime.h>
#include <cuda_bf16.h>
#include <cstdint>
#include <cstddef>

// ===========================================================================
// GCN via bf16-split warp MMA (mma.sync m16n8k16, fp32 accum).
//   A*B ~= Ahi*Bhi + Ahi*Blo + Alo*Bhi
// K-chunk 32, 3-stage ring, 96KB smem -> 2 CTAs/SM (16 warps/SM).
// ===========================================================================

#define NBAT 32
#define NNODE 1024
#define HMAX (NBAT * NNODE * 512)

__device__ __nv_bfloat16 g_adjh[NBAT * NNODE * NNODE];
__device__ __nv_bfloat16 g_adjl[NBAT * NNODE * NNODE];
__device__ __nv_bfloat16 g_h0h[HMAX], g_h0l[HMAX], g_h1h[HMAX], g_h1l[HMAX];
__device__ __nv_bfloat16 g_agh[HMAX], g_agl[HMAX];
__device__ float g_cls[NBAT * NNODE * 256];
__device__ __nv_bfloat16 g_wh[1310720], g_wl[1310720];

// ---------------------------------------------------------------------------
static __device__ __forceinline__ uint32_t s2u(const void* p) {
    uint32_t a;
    asm("{ .reg .u64 t; cvta.to.shared.u64 t, %1; cvt.u32.u64 %0, t; }" : "=r"(a) : "l"(p));
    return a;
}
static __device__ __forceinline__ void split2(float v, __nv_bfloat16& h, __nv_bfloat16& l) {
    h = __float2bfloat16(v);
    l = __float2bfloat16(v - __bfloat162float(h));
}

static __device__ __forceinline__ void cp16(uint32_t dst, const void* src) {
    asm volatile("cp.async.cg.shared.global [%0], [%1], 16;" :: "r"(dst), "l"(src));
}
static __device__ __forceinline__ void ldsm4(uint32_t* r, uint32_t addr) {
    asm volatile("ldmatrix.sync.aligned.m8n8.x4.shared.b16 {%0,%1,%2,%3}, [%4];"
                 : "=r"(r[0]), "=r"(r[1]), "=r"(r[2]), "=r"(r[3]) : "r"(addr));
}
static __device__ __forceinline__ void ldsm4t(uint32_t* r, uint32_t addr) {
    asm volatile("ldmatrix.sync.aligned.m8n8.x4.trans.shared.b16 {%0,%1,%2,%3}, [%4];"
                 : "=r"(r[0]), "=r"(r[1]), "=r"(r[2]), "=r"(r[3]) : "r"(addr));
}
static __device__ __forceinline__ void mma16816(float* c, const uint32_t* a, const uint32_t* b) {
    asm volatile(
        "mma.sync.aligned.m16n8k16.row.col.f32.bf16.bf16.f32 "
        "{%0,%1,%2,%3}, {%4,%5,%6,%7}, {%8,%9}, {%0,%1,%2,%3};"
        : "+f"(c[0]), "+f"(c[1]), "+f"(c[2]), "+f"(c[3])
        : "r"(a[0]), "r"(a[1]), "r"(a[2]), "r"(a[3]), "r"(b[0]), "r"(b[1]));
}

// A tile: 128 rows x 64B (k32). swizzled 16B-chunk offset, conflict-free for
// every aligned 8-row ldmatrix phase: seg' = seg ^ ((row>>1)&3)
static __device__ __forceinline__ uint32_t aswz(int row, int seg) {
    return (uint32_t)(row * 64 + ((seg ^ ((row >> 1) & 3)) * 16));
}

// ---------------------------------------------------------------------------
__global__ void split_kernel(const float4* __restrict__ src,
                             __nv_bfloat16* __restrict__ hi,
                             __nv_bfloat16* __restrict__ lo, int n4) {
    int i = blockIdx.x * blockDim.x + threadIdx.x;
    if (i >= n4) return;
    float4 v = src[i];
    __nv_bfloat16 h0, l0, h1, l1, h2, l2, h3, l3;
    split2(v.x, h0, l0); split2(v.y, h1, l1);
    split2(v.z, h2, l2); split2(v.w, h3, l3);
    __nv_bfloat162 a, b, c, d;
    a.x = h0; a.y = h1; b.x = h2; b.y = h3;
    c.x = l0; c.y = l1; d.x = l2; d.y = l3;
    __nv_bfloat162* ph = reinterpret_cast<__nv_bfloat162*>(hi) + (size_t)i * 2;
    __nv_bfloat162* pl = reinterpret_cast<__nv_bfloat162*>(lo) + (size_t)i * 2;
    ph[0] = a; ph[1] = b;
    pl[0] = c; pl[1] = d;
}

// ---------------------------------------------------------------------------
// Split-bf16 warp-MMA GEMM:  D[M,N] = A[M,K] @ B[K,N]  (row-major)
// A virtually split at ksplit. EPI: 0 split store, 1 bias+relu split, 3 bias+prelu fp32
// M,N mult of 128; K,ksplit mult of 32.
// ---------------------------------------------------------------------------
#define STGB 32768
#define NSTG 3
#define SMEM_BYTES (NSTG * STGB + 1024)

template <int EPI>
__global__ void __launch_bounds__(256, 2)
tc_gemm(const __nv_bfloat16* __restrict__ A0h, const __nv_bfloat16* __restrict__ A0l,
        const __nv_bfloat16* __restrict__ A1h, const __nv_bfloat16* __restrict__ A1l,
        int ksplit,
        const __nv_bfloat16* __restrict__ Bh, const __nv_bfloat16* __restrict__ Bl,
        const float* __restrict__ bias, const float* __restrict__ alpha,
        float* __restrict__ Cf,
        __nv_bfloat16* __restrict__ Chi, __nv_bfloat16* __restrict__ Clo,
        int M, int N, int K, long sA, long sB)
{
    extern __shared__ char smraw[];
    const int tid = threadIdx.x;
    const int bz = blockIdx.z;
    const int row0 = blockIdx.y * 128, col0 = blockIdx.x * 128;
    uint32_t sb0 = (s2u(smraw) + 1023u) & ~1023u;

    const __nv_bfloat16* A0hb = A0h + (size_t)bz * sA;
    const __nv_bfloat16* A0lb = A0l + (size_t)bz * sA;
    const __nv_bfloat16* A1hb = A1h + (size_t)bz * sA;
    const __nv_bfloat16* A1lb = A1l + (size_t)bz * sA;
    const __nv_bfloat16* Bhb  = Bh + (size_t)bz * sB;
    const __nv_bfloat16* Blb  = Bl + (size_t)bz * sB;
    const int NT = K >> 5;

    // per-thread load coords (stage = A 128x32 + B 32x128, hi+lo)
    const int ar = tid >> 1;            // A row 0..127
    const int acb = (tid & 1) * 2;      // A chunk base (of 4 16B chunks/row)
    const int bk = tid >> 3;            // B k-row 0..31
    const int bcb = (tid & 7) * 2;      // B chunk base (of 16 16B chunks/row)

    auto load_stage = [&](int t) {
        uint32_t ub = sb0 + (t % NSTG) * STGB;
        int k0 = t << 5;
        const __nv_bfloat16 *pAh, *pAl;
        int lda, kk;
        if (k0 < ksplit) { pAh = A0hb; pAl = A0lb; lda = ksplit; kk = k0; }
        else             { pAh = A1hb; pAl = A1lb; lda = K - ksplit; kk = k0 - ksplit; }
        const __nv_bfloat16* arh = pAh + (size_t)(row0 + ar) * lda + kk;
        const __nv_bfloat16* arl = pAl + (size_t)(row0 + ar) * lda + kk;
        const __nv_bfloat16* brh = Bhb + (size_t)(k0 + bk) * N + col0;
        const __nv_bfloat16* brl = Blb + (size_t)(k0 + bk) * N + col0;
#pragma unroll
        for (int c = 0; c < 2; c++) {
            uint32_t so = aswz(ar, acb + c);
            cp16(ub + so,        arh + (acb + c) * 8);
            cp16(ub + 8192 + so, arl + (acb + c) * 8);
            uint32_t bo = (uint32_t)(bk * 256 + (((bcb + c) ^ (bk & 7)) * 16));
            cp16(ub + 16384 + bo, brh + (bcb + c) * 8);
            cp16(ub + 24576 + bo, brl + (bcb + c) * 8);
        }
        asm volatile("cp.async.commit_group;" ::: "memory");
    };

    load_stage(0);
    if (NT > 1) load_stage(1);

    const int wid = tid >> 5, lane = tid & 31;
    const int m0 = (wid >> 2) * 64;      // warp m offset
    const int nw = (wid & 3) * 32;       // warp n offset

    float acc[4][4][4];
#pragma unroll
    for (int a = 0; a < 4; a++)
#pragma unroll
        for (int b = 0; b < 4; b++)
#pragma unroll
            for (int c = 0; c < 4; c++) acc[a][b][c] = 0.0f;

    const int a_row = (lane & 15);
    const int a_seg = (lane >> 4);
    const int b_row = (lane & 7) + ((lane >> 3) & 1) * 8;
    const int b_seg = (lane >> 4);

    for (int t = 0; t < NT; t++) {
        if (t < NT - 1) asm volatile("cp.async.wait_group 1;" ::: "memory");
        else            asm volatile("cp.async.wait_group 0;" ::: "memory");
        __syncthreads();
        if (t + 2 < NT) load_stage(t + 2);

        uint32_t ub = sb0 + (t % NSTG) * STGB;
#pragma unroll
        for (int k16 = 0; k16 < 2; k16++) {
            uint32_t Ah[4][4], Al[4][4];
#pragma unroll
            for (int mi = 0; mi < 4; mi++) {
                int row = m0 + mi * 16 + a_row;
                uint32_t off = aswz(row, k16 * 2 + a_seg);
                ldsm4(Ah[mi], ub + off);
                ldsm4(Al[mi], ub + 8192 + off);
            }
#pragma unroll
            for (int p = 0; p < 2; p++) {
                int kr = k16 * 16 + b_row;
                int nseg = ((nw + p * 16) >> 3) + b_seg;
                uint32_t off = (uint32_t)(kr * 256 + ((nseg ^ (kr & 7)) * 16));
                uint32_t Bh4[4], Bl4[4];
                ldsm4t(Bh4, ub + 16384 + off);
                ldsm4t(Bl4, ub + 24576 + off);
#pragma unroll
                for (int q = 0; q < 2; q++) {
                    const int ni = p * 2 + q;
#pragma unroll
                    for (int mi = 0; mi < 4; mi++) {
                        mma16816(acc[mi][ni], Ah[mi], &Bh4[q * 2]);
                        mma16816(acc[mi][ni], Ah[mi], &Bl4[q * 2]);
                        mma16816(acc[mi][ni], Al[mi], &Bh4[q * 2]);
                    }
                }
            }
        }
    }

    // ---- epilogue ----
    const int r_lane = lane >> 2;
    const int c_lane = (lane & 3) * 2;
#pragma unroll
    for (int mi = 0; mi < 4; mi++) {
#pragma unroll
        for (int ni = 0; ni < 4; ni++) {
            int rg = row0 + m0 + mi * 16 + r_lane;
            int cg = col0 + nw + ni * 8 + c_lane;
            long grow0 = (long)bz * M + rg;
            long grow1 = grow0 + 8;
            float v0 = acc[mi][ni][0], v1 = acc[mi][ni][1];
            float v2 = acc[mi][ni][2], v3 = acc[mi][ni][3];
            if (EPI == 1) {
                float bb0 = __ldg(bias + cg), bb1 = __ldg(bias + cg + 1);
                v0 = fmaxf(v0 + bb0, 0.0f); v1 = fmaxf(v1 + bb1, 0.0f);
                v2 = fmaxf(v2 + bb0, 0.0f); v3 = fmaxf(v3 + bb1, 0.0f);
            }
            if (EPI == 3) {
                float bb0 = __ldg(bias + cg), bb1 = __ldg(bias + cg + 1);
                float aa0 = __ldg(alpha + cg), aa1 = __ldg(alpha + cg + 1);
                v0 += bb0; v1 += bb1; v2 += bb0; v3 += bb1;
                v0 = v0 > 0.0f ? v0 : aa0 * v0;
                v1 = v1 > 0.0f ? v1 : aa1 * v1;
                v2 = v2 > 0.0f ? v2 : aa0 * v2;
                v3 = v3 > 0.0f ? v3 : aa1 * v3;
                float2 f0; f0.x = v0; f0.y = v1;
                float2 f1; f1.x = v2; f1.y = v3;
                *reinterpret_cast<float2*>(Cf + grow0 * N + cg) = f0;
                *reinterpret_cast<float2*>(Cf + grow1 * N + cg) = f1;
            } else {
                __nv_bfloat16 h0, l0, h1, l1, h2, l2, h3, l3;
                split2(v0, h0, l0); split2(v1, h1, l1);
                split2(v2, h2, l2); split2(v3, h3, l3);
                __nv_bfloat162 hp0, lp0, hp1, lp1;
                hp0.x = h0; hp0.y = h1; lp0.x = l0; lp0.y = l1;
                hp1.x = h2; hp1.y = h3; lp1.x = l2; lp1.y = l3;
                *reinterpret_cast<__nv_bfloat162*>(Chi + grow0 * N + cg) = hp0;
                *reinterpret_cast<__nv_bfloat162*>(Clo + grow0 * N + cg) = lp0;
                *reinterpret_cast<__nv_bfloat162*>(Chi + grow1 * N + cg) = hp1;
                *reinterpret_cast<__nv_bfloat162*>(Clo + grow1 * N + cg) = lp1;
            }
        }
    }
}

// ---------------------------------------------------------------------------
__global__ void cls2_kernel(const float* __restrict__ h, const float* __restrict__ W,
                            const float* __restrict__ bvec, float* __restrict__ out, int M)
{
    __shared__ float Ws[512];
    const int tid = threadIdx.x;
    for (int i = tid; i < 512; i += blockDim.x) Ws[i] = W[i];
    __syncthreads();
    const int r = blockIdx.x * blockDim.x + tid;
    if (r >= M) return;
    const float4* hr = reinterpret_cast<const float4*>(h + (size_t)r * 256);
    float s0 = bvec[0], s1 = bvec[1];
#pragma unroll 8
    for (int k4 = 0; k4 < 64; k4++) {
        float4 v = hr[k4];
        const int k = k4 * 4;
        s0 = fmaf(v.x, Ws[(k + 0) * 2 + 0], s0);
        s1 = fmaf(v.x, Ws[(k + 0) * 2 + 1], s1);
        s0 = fmaf(v.y, Ws[(k + 1) * 2 + 0], s0);
        s1 = fmaf(v.y, Ws[(k + 1) * 2 + 1], s1);
        s0 = fmaf(v.z, Ws[(k + 2) * 2 + 0], s0);
        s1 = fmaf(v.z, Ws[(k + 2) * 2 + 1], s1);
        s0 = fmaf(v.w, Ws[(k + 3) * 2 + 0], s0);
        s1 = fmaf(v.w, Ws[(k + 3) * 2 + 1], s1);
    }
    out[(size_t)r * 2 + 0] = s0;
    out[(size_t)r * 2 + 1] = s1;
}

// ---------------------------------------------------------------------------
extern "C" void kernel_launch(void* const* d_in, const int* in_sizes, int n_in,
                              void* d_out, int out_size)
{
    const float* x   = (const float*)d_in[0];
    const float* adj = (const float*)d_in[1];
    const float* W1  = (const float*)d_in[2];
    const float* b1  = (const float*)d_in[3];
    const float* W2  = (const float*)d_in[4];
    const float* b2  = (const float*)d_in[5];
    const float* W3  = (const float*)d_in[6];
    const float* b3  = (const float*)d_in[7];
    const float* W4  = (const float*)d_in[8];
    const float* b4  = (const float*)d_in[9];
    const float* cW1 = (const float*)d_in[10];
    const float* cb1 = (const float*)d_in[11];
    const float* alp = (const float*)d_in[12];
    const float* cW2 = (const float*)d_in[13];
    const float* cb2 = (const float*)d_in[14];
    float* out = (float*)d_out;

    cudaFuncSetAttribute(tc_gemm<0>, cudaFuncAttributeMaxDynamicSharedMemorySize, SMEM_BYTES);
    cudaFuncSetAttribute(tc_gemm<1>, cudaFuncAttributeMaxDynamicSharedMemorySize, SMEM_BYTES);
    cudaFuncSetAttribute(tc_gemm<3>, cudaFuncAttributeMaxDynamicSharedMemorySize, SMEM_BYTES);

    __nv_bfloat16 *adjh, *adjl, *h0h, *h0l, *h1h, *h1l, *agh, *agl, *wh, *wl;
    float* cls;
    cudaGetSymbolAddress((void**)&adjh, g_adjh);
    cudaGetSymbolAddress((void**)&adjl, g_adjl);
    cudaGetSymbolAddress((void**)&h0h, g_h0h);
    cudaGetSymbolAddress((void**)&h0l, g_h0l);
    cudaGetSymbolAddress((void**)&h1h, g_h1h);
    cudaGetSymbolAddress((void**)&h1l, g_h1l);
    cudaGetSymbolAddress((void**)&agh, g_agh);
    cudaGetSymbolAddress((void**)&agl, g_agl);
    cudaGetSymbolAddress((void**)&wh, g_wh);
    cudaGetSymbolAddress((void**)&wl, g_wl);
    cudaGetSymbolAddress((void**)&cls, g_cls);

    const long aS = (long)NNODE * NNODE;
    dim3 blk(256);

    // ---- prep: elementwise bf16 hi/lo splits
    split_kernel<<<(NBAT * NNODE * NNODE / 4 + 255) / 256, blk>>>(
        (const float4*)adj, adjh, adjl, NBAT * NNODE * NNODE / 4);
    split_kernel<<<(NBAT * NNODE * 256 / 4 + 255) / 256, blk>>>(
        (const float4*)x, h0h, h0l, NBAT * NNODE * 256 / 4);
    split_kernel<<<(262144 / 4 + 255) / 256, blk>>>((const float4*)W1, wh + 0, wl + 0, 65536);
    split_kernel<<<(524288 / 4 + 255) / 256, blk>>>((const float4*)W2, wh + 262144, wl + 262144, 131072);
    split_kernel<<<(262144 / 4 + 255) / 256, blk>>>((const float4*)W3, wh + 786432, wl + 786432, 65536);
    split_kernel<<<(131072 / 4 + 255) / 256, blk>>>((const float4*)W4, wh + 1048576, wl + 1048576, 32768);
    split_kernel<<<(65536 / 4 + 255) / 256, blk>>>((const float4*)cW1, wh + 1179648, wl + 1179648, 16384);

    // ---- Layer 1
    tc_gemm<0><<<dim3(2, 8, NBAT), blk, SMEM_BYTES>>>(
        adjh, adjl, adjh, adjl, 1024, h0h, h0l, nullptr, nullptr,
        nullptr, agh, agl, 1024, 256, 1024, aS, (long)NNODE * 256);
    tc_gemm<1><<<dim3(4, 256, 1), blk, SMEM_BYTES>>>(
        h0h, h0l, agh, agl, 256, wh + 0, wl + 0, b1, nullptr,
        nullptr, h1h, h1l, 32768, 512, 512, 0, 0);

    // ---- Layer 2
    tc_gemm<0><<<dim3(4, 8, NBAT), blk, SMEM_BYTES>>>(
        adjh, adjl, adjh, adjl, 1024, h1h, h1l, nullptr, nullptr,
        nullptr, agh, agl, 1024, 512, 1024, aS, (long)NNODE * 512);
    tc_gemm<1><<<dim3(4, 256, 1), blk, SMEM_BYTES>>>(
        h1h, h1l, agh, agl, 512, wh + 262144, wl + 262144, b2, nullptr,
        nullptr, h0h, h0l, 32768, 512, 1024, 0, 0);

    // ---- Layer 3
    tc_gemm<0><<<dim3(4, 8, NBAT), blk, SMEM_BYTES>>>(
        adjh, adjl, adjh, adjl, 1024, h0h, h0l, nullptr, nullptr,
        nullptr, agh, agl, 1024, 512, 1024, aS, (long)NNODE * 512);
    tc_gemm<1><<<dim3(2, 256, 1), blk, SMEM_BYTES>>>(
        h0h, h0l, agh, agl, 512, wh + 786432, wl + 786432, b3, nullptr,
        nullptr, h1h, h1l, 32768, 256, 1024, 0, 0);

    // ---- Layer 4
    tc_gemm<0><<<dim3(2, 8, NBAT), blk, SMEM_BYTES>>>(
        adjh, adjl, adjh, adjl, 1024, h1h, h1l, nullptr, nullptr,
        nullptr, agh, agl, 1024, 256, 1024, aS, (long)NNODE * 256);
    tc_gemm<1><<<dim3(2, 256, 1), blk, SMEM_BYTES>>>(
        h1h, h1l, agh, agl, 256, wh + 1048576, wl + 1048576, b4, nullptr,
        nullptr, h0h, h0l, 32768, 256, 512, 0, 0);

    // ---- Classifier
    tc_gemm<3><<<dim3(2, 256, 1), blk, SMEM_BYTES>>>(
        h0h, h0l, h0h, h0l, 256, wh + 1179648, wl + 1179648, cb1, alp,
        cls, nullptr, nullptr, 32768, 256, 256, 0, 0);
    cls2_kernel<<<dim3(128), blk>>>(cls, cW2, cb2, out, 32768);
}